// round 2
// baseline (speedup 1.0000x reference)
#include <cuda_runtime.h>
#include <cstdint>

// DistMult edge scorer:
//   out[e] = sigmoid( sum_d z[src[e],d] * rel[rel_id[e],d] * z[dst[e],d] )
// Inputs (metadata order):
//   d_in[0]: z          float32 [100000, 128]
//   d_in[1]: edge_index int32   [2, E]   (JAX x64 disabled -> int64 becomes int32)
//   d_in[2]: rel_id     int32   [E]
//   d_in[3]: rel        float32 [64, 128]
// Output: float32 [E]
//
// One warp per edge; lane l handles float4 chunk l of the 128-dim rows.
// Each z gather is a coalesced 512B warp transaction (4 lines). z (51MB)
// fits in L2, rel (32KB) fits in L1 -> steady-state replays are L2-bound.

#define D 128

__global__ __launch_bounds__(256) void distmult_kernel(
    const float* __restrict__ z,
    const int* __restrict__ edge_index,  // [2, E] int32
    const int* __restrict__ rel_id,      // [E] int32
    const float* __restrict__ rel,       // [64, 128]
    float* __restrict__ out,
    int E)
{
    int warp_id = (blockIdx.x * blockDim.x + threadIdx.x) >> 5;
    int lane = threadIdx.x & 31;
    if (warp_id >= E) return;

    // Broadcast index loads (all lanes same address -> L1 broadcast, free).
    int src = edge_index[warp_id];
    int dst = edge_index[E + warp_id];
    int r   = rel_id[warp_id];

    const float4* zs = reinterpret_cast<const float4*>(z + (size_t)src * D);
    const float4* zd = reinterpret_cast<const float4*>(z + (size_t)dst * D);
    const float4* rr = reinterpret_cast<const float4*>(rel + (size_t)r * D);

    float4 a = zs[lane];
    float4 b = zd[lane];
    float4 c = rr[lane];

    float acc = a.x * c.x * b.x
              + a.y * c.y * b.y
              + a.z * c.z * b.z
              + a.w * c.w * b.w;

    // Warp tree reduction
    #pragma unroll
    for (int off = 16; off > 0; off >>= 1)
        acc += __shfl_xor_sync(0xFFFFFFFFu, acc, off);

    if (lane == 0) {
        float s = 1.0f / (1.0f + __expf(-acc));
        out[warp_id] = s;
    }
}

extern "C" void kernel_launch(void* const* d_in, const int* in_sizes, int n_in,
                              void* d_out, int out_size)
{
    const float* z          = (const float*)d_in[0];
    const int*   edge_index = (const int*)d_in[1];
    const int*   rel_id     = (const int*)d_in[2];
    const float* rel        = (const float*)d_in[3];
    float*       out        = (float*)d_out;

    int E = in_sizes[2];  // rel_id has E elements

    const int threads = 256;  // 8 warps (8 edges) per block
    int warps_per_block = threads / 32;
    int blocks = (E + warps_per_block - 1) / warps_per_block;

    distmult_kernel<<<blocks, threads>>>(z, edge_index, rel_id, rel, out, E);
}

// round 3
// speedup vs baseline: 1.8259x; 1.8259x over previous
#include <cuda_runtime.h>
#include <cstdint>

// DistMult edge scorer:
//   out[e] = sigmoid( sum_d z[src[e],d] * rel[rel_id[e],d] * z[dst[e],d] )
// Inputs (metadata order):
//   d_in[0]: z          float32 [100000, 128]
//   d_in[1]: edge_index int32   [2, E]
//   d_in[2]: rel_id     int32   [E]
//   d_in[3]: rel        float32 [64, 128]
// Output: float32 [E]
//
// Each warp processes 32 consecutive edges:
//  - 3 coalesced index loads cover all 32 edges (vs 3 broadcast loads/edge)
//  - per edge: 2 z-gathers + 1 rel load (512B warp transactions, the floor)
//  - butterfly reduction leaves sum in all lanes; lane i keeps edge i's score
//  - ONE coalesced 128B store for 32 edges, sigmoid once per lane

#define D 128
#define FULL 0xFFFFFFFFu

__global__ __launch_bounds__(256) void distmult_kernel(
    const float* __restrict__ z,
    const int* __restrict__ edge_index,  // [2, E]
    const int* __restrict__ rel_id,      // [E]
    const float* __restrict__ rel,       // [64, 128]
    float* __restrict__ out,
    int E)
{
    int warp_id = (blockIdx.x * blockDim.x + threadIdx.x) >> 5;
    int lane = threadIdx.x & 31;
    int base = warp_id << 5;             // first edge of this warp's batch
    if (base >= E) return;

    // Coalesced index loads: lane l holds edge (base+l)'s indices.
    int my_e = base + lane;
    bool valid = my_e < E;
    int safe_e = valid ? my_e : base;    // clamp for tail warp
    int my_src = edge_index[safe_e];
    int my_dst = edge_index[E + safe_e];
    int my_rel = rel_id[safe_e];

    float score = 0.0f;                  // lane i ends up with edge base+i's score

    // Prologue: load rows for edge 0
    int s = __shfl_sync(FULL, my_src, 0);
    int d = __shfl_sync(FULL, my_dst, 0);
    int r = __shfl_sync(FULL, my_rel, 0);
    float4 a = reinterpret_cast<const float4*>(z   + (size_t)s * D)[lane];
    float4 b = reinterpret_cast<const float4*>(z   + (size_t)d * D)[lane];
    float4 c = reinterpret_cast<const float4*>(rel + (size_t)r * D)[lane];

    #pragma unroll 4
    for (int i = 0; i < 32; ++i) {
        float4 ca = a, cb = b, cc = c;

        // Prefetch next edge's rows before reducing the current one,
        // keeping 3 loads in flight while the 5-shfl reduction runs.
        if (i < 31) {
            int ns = __shfl_sync(FULL, my_src, i + 1);
            int nd = __shfl_sync(FULL, my_dst, i + 1);
            int nr = __shfl_sync(FULL, my_rel, i + 1);
            a = reinterpret_cast<const float4*>(z   + (size_t)ns * D)[lane];
            b = reinterpret_cast<const float4*>(z   + (size_t)nd * D)[lane];
            c = reinterpret_cast<const float4*>(rel + (size_t)nr * D)[lane];
        }

        float p = ca.x * cc.x * cb.x
                + ca.y * cc.y * cb.y
                + ca.z * cc.z * cb.z
                + ca.w * cc.w * cb.w;

        // Butterfly reduction: full sum lands in every lane.
        #pragma unroll
        for (int off = 16; off > 0; off >>= 1)
            p += __shfl_xor_sync(FULL, p, off);

        if (lane == i) score = p;
    }

    // One sigmoid + one coalesced store per lane (covers 32 edges).
    if (valid)
        out[my_e] = 1.0f / (1.0f + __expf(-score));
}

extern "C" void kernel_launch(void* const* d_in, const int* in_sizes, int n_in,
                              void* d_out, int out_size)
{
    const float* z          = (const float*)d_in[0];
    const int*   edge_index = (const int*)d_in[1];
    const int*   rel_id     = (const int*)d_in[2];
    const float* rel        = (const float*)d_in[3];
    float*       out        = (float*)d_out;

    int E = in_sizes[2];  // rel_id has E elements

    const int threads = 256;                  // 8 warps/block, 32 edges/warp
    int edges_per_block = (threads / 32) * 32;
    int blocks = (E + edges_per_block - 1) / edges_per_block;

    distmult_kernel<<<blocks, threads>>>(z, edge_index, rel_id, rel, out, E);
}

// round 4
// speedup vs baseline: 2.3727x; 1.2995x over previous
#include <cuda_runtime.h>
#include <cstdint>

// DistMult edge scorer:
//   out[e] = sigmoid( sum_d z[src[e],d] * rel[rel_id[e],d] * z[dst[e],d] )
// Inputs:
//   d_in[0]: z          float32 [100000, 128]
//   d_in[1]: edge_index int32   [2, E]
//   d_in[2]: rel_id     int32   [E]
//   d_in[3]: rel        float32 [64, 128]
// Output: float32 [E]
//
// Layout: 8 lanes per edge, 4 edges per warp-pass, 8 passes per warp
// (32 edges/warp). Lane j of group g loads float4 chunks {j, j+8, j+16, j+24}
// of edge g's rows -> every warp load instruction covers 4 full 128B lines
// (4 wavefronts, max efficiency). Reduction is 3 shfl levels for 4 edges at
// once (0.75 shfl/edge vs 5). Index loads are group-uniform (broadcast within
// one wavefront), no index shuffles.

#define D 128
#define FULL 0xFFFFFFFFu

__device__ __forceinline__ float tprod(float4 a, float4 c, float4 b) {
    return a.x * c.x * b.x
         + a.y * c.y * b.y
         + a.z * c.z * b.z
         + a.w * c.w * b.w;
}

__global__ __launch_bounds__(256) void distmult_kernel(
    const float* __restrict__ z,
    const int* __restrict__ edge_index,  // [2, E]
    const int* __restrict__ rel_id,      // [E]
    const float* __restrict__ rel,       // [64, 128]
    float* __restrict__ out,
    int E)
{
    int warp_id = (blockIdx.x * blockDim.x + threadIdx.x) >> 5;
    int lane = threadIdx.x & 31;
    int g = lane >> 3;                   // edge group 0..3
    int j = lane & 7;                    // lane within group
    int base = warp_id << 5;             // 32 edges per warp
    if (base >= E) return;

    #pragma unroll 1
    for (int m = 0; m < 8; ++m) {
        int e = base + (m << 2) + g;
        if (e >= E) break;               // E % 32 == 0 in practice; safe anyway

        // Group-uniform index loads: 4 consecutive values per warp instruction,
        // broadcast to 8 lanes each -> single wavefront.
        int s = edge_index[e];
        int d = edge_index[E + e];
        int r = rel_id[e];

        const float4* zs = reinterpret_cast<const float4*>(z   + (size_t)s * D);
        const float4* zd = reinterpret_cast<const float4*>(z   + (size_t)d * D);
        const float4* rr = reinterpret_cast<const float4*>(rel + (size_t)r * D);

        // 12 independent 16B loads -> deep MLP, full-line wavefronts.
        float4 a0 = zs[j],      a1 = zs[j + 8],  a2 = zs[j + 16], a3 = zs[j + 24];
        float4 b0 = zd[j],      b1 = zd[j + 8],  b2 = zd[j + 16], b3 = zd[j + 24];
        float4 c0 = rr[j],      c1 = rr[j + 8],  c2 = rr[j + 16], c3 = rr[j + 24];

        float acc = tprod(a0, c0, b0)
                  + tprod(a1, c1, b1)
                  + tprod(a2, c2, b2)
                  + tprod(a3, c3, b3);

        // Reduce over the 8-lane group; 4 edges reduce in the same 3 shfls.
        acc += __shfl_xor_sync(FULL, acc, 4);
        acc += __shfl_xor_sync(FULL, acc, 2);
        acc += __shfl_xor_sync(FULL, acc, 1);

        if (j == 0) {
            // Lanes 0,8,16,24 store 4 consecutive floats -> one wavefront.
            out[e] = 1.0f / (1.0f + __expf(-acc));
        }
    }
}

extern "C" void kernel_launch(void* const* d_in, const int* in_sizes, int n_in,
                              void* d_out, int out_size)
{
    const float* z          = (const float*)d_in[0];
    const int*   edge_index = (const int*)d_in[1];
    const int*   rel_id     = (const int*)d_in[2];
    const float* rel        = (const float*)d_in[3];
    float*       out        = (float*)d_out;

    int E = in_sizes[2];  // rel_id has E elements

    const int threads = 256;                  // 8 warps/block, 32 edges/warp
    int edges_per_block = (threads / 32) * 32;
    int blocks = (E + edges_per_block - 1) / edges_per_block;

    distmult_kernel<<<blocks, threads>>>(z, edge_index, rel_id, rel, out, E);
}

// round 5
// speedup vs baseline: 3.0712x; 1.2944x over previous
#include <cuda_runtime.h>
#include <cuda_fp16.h>
#include <cstdint>

// DistMult edge scorer:
//   out[e] = sigmoid( sum_d z[src,d] * rel[rel_id,d] * z[dst,d] )
// Inputs:
//   d_in[0]: z          float32 [100000, 128]
//   d_in[1]: edge_index int32   [2, E]
//   d_in[2]: rel_id     int32   [E]
//   d_in[3]: rel        float32 [64, 128]
// Output: float32 [E]
//
// Two kernels per launch (graph-capturable):
//  1) convert_kernel: z, rel -> fp16 mirrors in __device__ globals (~10us).
//  2) distmult_h: gather fp16 rows (256B each = 2 lines). 8 lanes/edge,
//     4 edges per warp-pass; every load instruction covers 4 full 128B
//     lines. L1 wavefronts drop from ~13.25 to ~7.25 per edge.
// Accumulation in fp32 (HMUL2 src*rel, then cvt + FFMA with dst).

#define D 128
#define NZ_MAX (100000 * D)
#define NR_MAX (64 * D)
#define FULL 0xFFFFFFFFu

__device__ __half g_zh[NZ_MAX];
__device__ __half g_rh[NR_MAX];

// ---------------- conversion: fp32 -> fp16 mirrors ----------------
__global__ __launch_bounds__(256) void convert_kernel(
    const float* __restrict__ z, const float* __restrict__ rel,
    int nz, int nr)
{
    int i = blockIdx.x * blockDim.x + threadIdx.x;   // 4 floats per thread
    int nz4 = nz >> 2;
    int nr4 = nr >> 2;
    if (i < nz4) {
        float4 v = reinterpret_cast<const float4*>(z)[i];
        __half2 lo = __floats2half2_rn(v.x, v.y);
        __half2 hi = __floats2half2_rn(v.z, v.w);
        uint2 o;
        o.x = *reinterpret_cast<unsigned*>(&lo);
        o.y = *reinterpret_cast<unsigned*>(&hi);
        reinterpret_cast<uint2*>(g_zh)[i] = o;
    } else if (i < nz4 + nr4) {
        int k = i - nz4;
        float4 v = reinterpret_cast<const float4*>(rel)[k];
        __half2 lo = __floats2half2_rn(v.x, v.y);
        __half2 hi = __floats2half2_rn(v.z, v.w);
        uint2 o;
        o.x = *reinterpret_cast<unsigned*>(&lo);
        o.y = *reinterpret_cast<unsigned*>(&hi);
        reinterpret_cast<uint2*>(g_rh)[k] = o;
    }
}

// ---------------- main kernel ----------------

// acc += sum over the 2 halves packed in (a,c,b) words: fp16 mul src*rel,
// then fp32 FMA with dst.
__device__ __forceinline__ float dot2(unsigned a, unsigned c, unsigned b, float acc)
{
    __half2 ha = *reinterpret_cast<__half2*>(&a);
    __half2 hc = *reinterpret_cast<__half2*>(&c);
    __half2 hb = *reinterpret_cast<__half2*>(&b);
    __half2 t  = __hmul2(ha, hc);
    float2 tf = __half22float2(t);
    float2 bf = __half22float2(hb);
    acc = fmaf(tf.x, bf.x, acc);
    acc = fmaf(tf.y, bf.y, acc);
    return acc;
}

__device__ __forceinline__ float dot16(uint4 a, uint4 c, uint4 b, float acc)
{
    acc = dot2(a.x, c.x, b.x, acc);
    acc = dot2(a.y, c.y, b.y, acc);
    acc = dot2(a.z, c.z, b.z, acc);
    acc = dot2(a.w, c.w, b.w, acc);
    return acc;
}

__global__ __launch_bounds__(256) void distmult_h(
    const int* __restrict__ edge_index,  // [2, E]
    const int* __restrict__ rel_id,      // [E]
    float* __restrict__ out,
    int E)
{
    int warp_id = (blockIdx.x * blockDim.x + threadIdx.x) >> 5;
    int lane = threadIdx.x & 31;
    int g = lane >> 3;                   // edge group 0..3
    int j = lane & 7;                    // lane within group
    int base = warp_id << 5;             // 32 edges per warp
    if (base >= E) return;

    const uint4* zh = reinterpret_cast<const uint4*>(g_zh);   // 16 uint4 per row
    const uint4* rh = reinterpret_cast<const uint4*>(g_rh);

    #pragma unroll 2
    for (int m = 0; m < 8; ++m) {
        int e = base + (m << 2) + g;
        if (e >= E) break;

        // Group-uniform index loads (4 consecutive values/warp instr).
        int s = edge_index[e];
        int d = edge_index[E + e];
        int r = rel_id[e];

        const uint4* zs = zh + (size_t)s * 16;
        const uint4* zd = zh + (size_t)d * 16;
        const uint4* rr = rh + (size_t)r * 16;

        // 6 independent 16B loads; each warp instr = 4 full 128B lines.
        uint4 A0 = zs[j], A1 = zs[j + 8];
        uint4 B0 = zd[j], B1 = zd[j + 8];
        uint4 C0 = rr[j], C1 = rr[j + 8];

        float acc = 0.0f;
        acc = dot16(A0, C0, B0, acc);
        acc = dot16(A1, C1, B1, acc);

        // Reduce over 8-lane group; 4 edges share the same 3 shfls.
        acc += __shfl_xor_sync(FULL, acc, 4);
        acc += __shfl_xor_sync(FULL, acc, 2);
        acc += __shfl_xor_sync(FULL, acc, 1);

        if (j == 0) {
            // Lanes 0,8,16,24 -> 4 consecutive floats, one wavefront.
            out[e] = 1.0f / (1.0f + __expf(-acc));
        }
    }
}

extern "C" void kernel_launch(void* const* d_in, const int* in_sizes, int n_in,
                              void* d_out, int out_size)
{
    const float* z          = (const float*)d_in[0];
    const int*   edge_index = (const int*)d_in[1];
    const int*   rel_id     = (const int*)d_in[2];
    const float* rel        = (const float*)d_in[3];
    float*       out        = (float*)d_out;

    int nz = in_sizes[0];            // z element count (<= NZ_MAX)
    int nr = in_sizes[3];            // rel element count
    int E  = in_sizes[2];

    if (nz > NZ_MAX) nz = NZ_MAX;
    if (nr > NR_MAX) nr = NR_MAX;

    // 1) fp32 -> fp16 mirrors
    {
        int work = (nz >> 2) + (nr >> 2);
        int threads = 256;
        int blocks = (work + threads - 1) / threads;
        convert_kernel<<<blocks, threads>>>(z, rel, nz, nr);
    }

    // 2) edge scoring
    {
        const int threads = 256;                 // 8 warps/block, 32 edges/warp
        int edges_per_block = (threads / 32) * 32;
        int blocks = (E + edges_per_block - 1) / edges_per_block;
        distmult_h<<<blocks, threads>>>(edge_index, rel_id, out, E);
    }
}